// round 15
// baseline (speedup 1.0000x reference)
#include <cuda_runtime.h>
#include <cuda_bf16.h>
#include <cuda_fp16.h>
#include <cstdint>

#define D 128
#define MAXN 50000
#define MAXE 800000
#define XPAD 132   // W row pad (tf32 words)
#define HPAD 68    // X half-row pad

// Scratch (allocation-free rule: __device__ globals)
__device__ __half g_fj[MAXN * D];
__device__ float g_a1[MAXN];
__device__ float g_a2[MAXN];
__device__ int   g_cnt[MAXN];       // zeroed at end of scanB (starts zero)
__device__ int   g_rowptr[MAXN + 1];
__device__ int   g_slot[MAXE];      // within-bucket slot per edge (from hist)
__device__ int2  g_edge[MAXE];      // packed (col j, att bits)
__device__ int   g_bsum[256];

__device__ __forceinline__ float sigmoidf_(float x) {
    return 1.0f / (1.0f + __expf(-x));
}

__device__ __forceinline__ uint32_t f2tf32(float x) {
    uint32_t r;
    asm("cvt.rna.tf32.f32 %0, %1;" : "=r"(r) : "f"(x));
    return r;
}

__device__ __forceinline__ void mma_tf32(float& d0, float& d1, float& d2, float& d3,
                                         uint32_t a0, uint32_t a1, uint32_t a2, uint32_t a3,
                                         uint32_t b0, uint32_t b1) {
    asm volatile("mma.sync.aligned.m16n8k8.row.col.f32.tf32.tf32.f32 "
                 "{%0,%1,%2,%3},{%4,%5,%6,%7},{%8,%9},{%0,%1,%2,%3};"
                 : "+f"(d0), "+f"(d1), "+f"(d2), "+f"(d3)
                 : "r"(a0), "r"(a1), "r"(a2), "r"(a3), "r"(b0), "r"(b1));
}

#define LDSM4(r0, r1, r2, r3, addr)                                        \
    asm volatile("ldmatrix.sync.aligned.m8n8.x4.shared.b16 {%0,%1,%2,%3}, [%4];" \
                 : "=r"(r0), "=r"(r1), "=r"(r2), "=r"(r3) : "r"(addr))

// ---------------------------------------------------------------------------
// Edge histogram (side stream, hidden under GEMM). The atomic's return value
// IS the edge's within-bucket slot -> saved for the atomic-free fill.
// ---------------------------------------------------------------------------
__global__ __launch_bounds__(256)
void hist_kernel(const int* __restrict__ ei, int E, int N)
{
    int e = blockIdx.x * blockDim.x + threadIdx.x;
    if (e >= E) return;
    int i = ei[e];
    int slot = ((unsigned)i < (unsigned)N) ? atomicAdd(&g_cnt[i], 1) : 0;
    g_slot[e] = slot;
}

// ---------------------------------------------------------------------------
// Persistent tf32 GEMM (512 thr, 16 warps = 4 wm x 4 wn, warp tile 32x64),
// cp.async k-split double-buffered X from raw fp32 (rz trunc); W converted
// to tf32 in-kernel during staging (once per CTA).
// ---------------------------------------------------------------------------
__device__ __forceinline__ void stage_x_half(const float* __restrict__ X,
                                             int row0, int h, uint32_t xsh,
                                             int N, int tid)
{
#pragma unroll
    for (int it = 0; it < 4; ++it) {
        int idx = tid + it * 512;          // 0..2047
        int r   = idx >> 4;                // 0..127
        int c16 = idx & 15;                // 0..15 (16B units)
        int row = row0 + r;
        const float* gsrc = X + (size_t)((row < N) ? row : 0) * 128 + h * 64 + c16 * 4;
        uint32_t dst = xsh + (uint32_t)(r * HPAD + c16 * 4) * 4;
        uint32_t ssz = (row < N) ? 16u : 0u;
        asm volatile("cp.async.cg.shared.global [%0], [%1], 16, %2;"
                     :: "r"(dst), "l"(gsrc), "r"(ssz) : "memory");
    }
    asm volatile("cp.async.commit_group;" ::: "memory");
}

__device__ __forceinline__ void mma_half(float d[2][8][4],
                                         const uint32_t aaddr[2],
                                         const uint32_t baddr[4],
                                         uint32_t hoff)
{
#pragma unroll
    for (int kk = 0; kk < 8; ++kk) {
        const uint32_t koff = kk * 32;
        uint32_t a[2][4];
        LDSM4(a[0][0], a[0][1], a[0][2], a[0][3], aaddr[0] + koff);
        LDSM4(a[1][0], a[1][1], a[1][2], a[1][3], aaddr[1] + koff);
        uint32_t b[4][4];
        LDSM4(b[0][0], b[0][1], b[0][2], b[0][3], baddr[0] + hoff + koff);
        LDSM4(b[1][0], b[1][1], b[1][2], b[1][3], baddr[1] + hoff + koff);
        LDSM4(b[2][0], b[2][1], b[2][2], b[2][3], baddr[2] + hoff + koff);
        LDSM4(b[3][0], b[3][1], b[3][2], b[3][3], baddr[3] + hoff + koff);
#pragma unroll
        for (int t = 0; t < 2; ++t)
#pragma unroll
            for (int u = 0; u < 8; ++u)
                mma_tf32(d[t][u][0], d[t][u][1], d[t][u][2], d[t][u][3],
                         a[t][0], a[t][1], a[t][2], a[t][3],
                         b[u >> 1][(u & 1) * 2], b[u >> 1][(u & 1) * 2 + 1]);
    }
}

__global__ __launch_bounds__(512, 1)
void gat_gemm_kernel(const float* __restrict__ X,
                     const float* __restrict__ W1, const float* __restrict__ W2,
                     const float* __restrict__ b1, const float* __restrict__ b2,
                     const float* __restrict__ wa1, const float* __restrict__ ba1,
                     const float* __restrict__ wa2, const float* __restrict__ ba2,
                     float* __restrict__ out, int N, int tiles)
{
    extern __shared__ uint32_t smem_u[];
    uint32_t* ws  = smem_u;                          // [256][XPAD]
    uint32_t* xs0 = smem_u + 256 * XPAD;             // [128][HPAD]
    uint32_t* xs1 = xs0 + 128 * HPAD;                // [128][HPAD]
    float*    sp1 = (float*)(xs1 + 128 * HPAD);      // [128][4]
    float*    sp2 = sp1 + 128 * 4;                   // [128][4]

    const int tid  = threadIdx.x;
    const int warp = tid >> 5;
    const int lane = tid & 31;
    const int g    = lane >> 2;
    const int tig  = lane & 3;
    const int wm   = warp & 3;
    const int wn   = warp >> 2;
    const int m0   = wm * 32;

    // --- Stage W once, converting fp32 -> tf32 bits in-flight ---
    const float4* W1v = (const float4*)W1;
    const float4* W2v = (const float4*)W2;
    for (int it = 0; it < 8; ++it) {
        int idx = tid + it * 512;          // 0..4095: c 0..127, k4 0..31
        int c  = idx >> 5;
        int k4 = idx & 31;
        float4 a = W1v[c * 32 + k4];
        uint32_t* p = &ws[c * XPAD + k4 * 4];
        p[0] = f2tf32(a.x); p[1] = f2tf32(a.y); p[2] = f2tf32(a.z); p[3] = f2tf32(a.w);
        float4 b = W2v[c * 32 + k4];
        uint32_t* q = &ws[(128 + c) * XPAD + k4 * 4];
        q[0] = f2tf32(b.x); q[1] = f2tf32(b.y); q[2] = f2tf32(b.z); q[3] = f2tf32(b.w);
    }

    // --- ldmatrix per-lane addresses ---
    uint32_t aaddr[2][2];   // [buf][t]
    {
        int s = lane >> 3;
        int row = m0 + (lane & 7) + (s & 1) * 8;
        int colw = (s >> 1) * 4;
        aaddr[0][0] = (uint32_t)__cvta_generic_to_shared(&xs0[row * HPAD + colw]);
        aaddr[0][1] = (uint32_t)__cvta_generic_to_shared(&xs0[(row + 16) * HPAD + colw]);
        aaddr[1][0] = (uint32_t)__cvta_generic_to_shared(&xs1[row * HPAD + colw]);
        aaddr[1][1] = (uint32_t)__cvta_generic_to_shared(&xs1[(row + 16) * HPAD + colw]);
    }
    uint32_t baddr[4];
    {
        int s = lane >> 3;
        int khw = (s & 1) * 4;
#pragma unroll
        for (int p = 0; p < 4; ++p) {
            int u = 2 * p + (s >> 1);
            int n = (u < 4) ? (wn * 32 + u * 8) : (128 + wn * 32 + (u - 4) * 8);
            baddr[p] = (uint32_t)__cvta_generic_to_shared(&ws[(n + (lane & 7)) * XPAD + khw]);
        }
    }
    uint32_t xsh[2] = { (uint32_t)__cvta_generic_to_shared(xs0),
                        (uint32_t)__cvta_generic_to_shared(xs1) };

    // Per-thread epilogue constants
    float2 bb1[4], bb2[4], v1[4], v2[4];
#pragma unroll
    for (int u = 0; u < 4; ++u) {
        int c = wn * 32 + u * 8 + tig * 2;
        bb1[u] = *(const float2*)&b1[c];
        bb2[u] = *(const float2*)&b2[c];
        v1[u]  = *(const float2*)&wa1[c];
        v2[u]  = *(const float2*)&wa2[c];
    }
    const float bba1 = ba1[0];
    const float bba2 = ba2[0];

    int tile = blockIdx.x;
    stage_x_half(X, tile * 128, 0, xsh[0], N, tid);

    for (; tile < tiles; tile += gridDim.x) {
        const int row0 = tile * 128;

        stage_x_half(X, row0, 1, xsh[1], N, tid);
        asm volatile("cp.async.wait_group 1;" ::: "memory");   // half0 ready
        __syncthreads();                                       // S1 (also W visible)

        float d[2][8][4];
#pragma unroll
        for (int t = 0; t < 2; ++t)
#pragma unroll
            for (int u = 0; u < 8; ++u)
#pragma unroll
                for (int e = 0; e < 4; ++e) d[t][u][e] = 0.f;

        mma_half(d, aaddr[0], baddr, 0);
        __syncthreads();                                       // S2: buf0 free

        int ntile = tile + gridDim.x;
        if (ntile < tiles) {
            stage_x_half(X, ntile * 128, 0, xsh[0], N, tid);
            asm volatile("cp.async.wait_group 1;" ::: "memory"); // half1 ready
        } else {
            asm volatile("cp.async.wait_group 0;" ::: "memory");
        }
        __syncthreads();                                       // S3

        mma_half(d, aaddr[1], baddr, 64 * 4);

        // --- Dot partials, reduce over tig, stash per (row, wn) ---
        float p1[2][2] = {{0.f, 0.f}, {0.f, 0.f}};
        float p2[2][2] = {{0.f, 0.f}, {0.f, 0.f}};
#pragma unroll
        for (int t = 0; t < 2; ++t)
#pragma unroll
            for (int u = 0; u < 4; ++u) {
                float fi0 = fmaxf(d[t][u][0] + bb1[u].x, 0.f);
                float fi1 = fmaxf(d[t][u][1] + bb1[u].y, 0.f);
                float fi2 = fmaxf(d[t][u][2] + bb1[u].x, 0.f);
                float fi3 = fmaxf(d[t][u][3] + bb1[u].y, 0.f);
                float fj0 = fmaxf(d[t][u + 4][0] + bb2[u].x, 0.f);
                float fj1 = fmaxf(d[t][u + 4][1] + bb2[u].y, 0.f);
                float fj2 = fmaxf(d[t][u + 4][2] + bb2[u].x, 0.f);
                float fj3 = fmaxf(d[t][u + 4][3] + bb2[u].y, 0.f);
                p1[t][0] = fmaf(fi0, v1[u].x, fmaf(fi1, v1[u].y, p1[t][0]));
                p1[t][1] = fmaf(fi2, v1[u].x, fmaf(fi3, v1[u].y, p1[t][1]));
                p2[t][0] = fmaf(fj0, v2[u].x, fmaf(fj1, v2[u].y, p2[t][0]));
                p2[t][1] = fmaf(fj2, v2[u].x, fmaf(fj3, v2[u].y, p2[t][1]));
            }
#pragma unroll
        for (int off = 1; off <= 2; off <<= 1)
#pragma unroll
            for (int t = 0; t < 2; ++t)
#pragma unroll
                for (int h = 0; h < 2; ++h) {
                    p1[t][h] += __shfl_xor_sync(0xffffffffu, p1[t][h], off);
                    p2[t][h] += __shfl_xor_sync(0xffffffffu, p2[t][h], off);
                }
        if (tig == 0) {
#pragma unroll
            for (int t = 0; t < 2; ++t)
#pragma unroll
                for (int h = 0; h < 2; ++h) {
                    int r = m0 + t * 16 + g + h * 8;
                    sp1[r * 4 + wn] = p1[t][h];
                    sp2[r * 4 + wn] = p2[t][h];
                }
        }
        __syncthreads();                                       // S4: partials

        // --- att per thread; stores ---
#pragma unroll
        for (int t = 0; t < 2; ++t)
#pragma unroll
            for (int h = 0; h < 2; ++h) {
                int r = m0 + t * 16 + g + h * 8;
                int gr = row0 + r;
                if (gr >= N) continue;
                float a1v = sp1[r * 4] + sp1[r * 4 + 1] + sp1[r * 4 + 2] + sp1[r * 4 + 3] + bba1;
                float a2v = sp2[r * 4] + sp2[r * 4 + 1] + sp2[r * 4 + 2] + sp2[r * 4 + 3] + bba2;
                float att = sigmoidf_(a1v + a2v);
                if (wn == 0 && tig == 0) { g_a1[gr] = a1v; g_a2[gr] = a2v; }
                float*  orow = out  + (size_t)gr * D;
                __half* jrow = g_fj + (size_t)gr * D;
#pragma unroll
                for (int u = 0; u < 4; ++u) {
                    int c = wn * 32 + u * 8 + tig * 2;
                    int e0 = h * 2, e1 = h * 2 + 1;
                    float fj0 = fmaxf(d[t][u + 4][e0] + bb2[u].x, 0.f);
                    float fj1 = fmaxf(d[t][u + 4][e1] + bb2[u].y, 0.f);
                    float o0 = fmaf(att, fj0, fmaxf(d[t][u][e0] + bb1[u].x, 0.f));
                    float o1 = fmaf(att, fj1, fmaxf(d[t][u][e1] + bb1[u].y, 0.f));
                    *(float2*)&orow[c] = make_float2(o0, o1);
                    *(__half2*)&jrow[c] = __floats2half2_rn(fj0, fj1);
                }
            }
    }
}

// ---------------------------------------------------------------------------
// CSR build (side stream: hist -> scan1 -> scanB)
// ---------------------------------------------------------------------------
__global__ __launch_bounds__(256)
void scan1_kernel(int N) {
    __shared__ int red[256];
    int i = blockIdx.x * 256 + threadIdx.x;
    int v = (i < N) ? g_cnt[i] : 0;
    red[threadIdx.x] = v;
    __syncthreads();
    for (int off = 128; off >= 1; off >>= 1) {
        if (threadIdx.x < off) red[threadIdx.x] += red[threadIdx.x + off];
        __syncthreads();
    }
    if (threadIdx.x == 0) g_bsum[blockIdx.x] = red[0];
}

__global__ __launch_bounds__(256)
void scanB_kernel(int nb, int N) {
    __shared__ int p[256];
    __shared__ int boff;
    const int t = threadIdx.x;

    int v = (t < nb) ? g_bsum[t] : 0;
    p[t] = v;
    __syncthreads();
    for (int off = 1; off < 256; off <<= 1) {
        int u = (t >= off) ? p[t - off] : 0;
        __syncthreads();
        p[t] += u;
        __syncthreads();
    }
    if (t == (int)blockIdx.x) boff = p[t] - v;
    if (blockIdx.x == 0 && t == nb - 1) g_rowptr[N] = p[t];
    __syncthreads();

    int i = blockIdx.x * 256 + t;
    int c = (i < N) ? g_cnt[i] : 0;
    p[t] = c;
    __syncthreads();
    for (int off = 1; off < 256; off <<= 1) {
        int u = (t >= off) ? p[t - off] : 0;
        __syncthreads();
        p[t] += u;
        __syncthreads();
    }
    if (i < N) {
        g_rowptr[i] = p[t] - c + boff;
        g_cnt[i] = 0;      // leave zeroed for next launch (determinism)
    }
}

// Fill CSR: NO atomics — pos = rowptr[i] + slot[e] (slot from hist).
__global__ void fill_kernel(const int* __restrict__ ei, int E, int N) {
    int e = blockIdx.x * blockDim.x + threadIdx.x;
    if (e >= E) return;
    int i = ei[e];
    int j = ei[E + e];
    if ((unsigned)i >= (unsigned)N || (unsigned)j >= (unsigned)N) return;
    int pos = g_rowptr[i] + g_slot[e];
    float att = sigmoidf_(g_a1[i] + g_a2[j]);
    g_edge[pos] = make_int2(j, __float_as_int(att));
}

// ---------------------------------------------------------------------------
// Gather: one warp per node; shfl-broadcast of packed (col, attw) pairs.
// ---------------------------------------------------------------------------
__global__ __launch_bounds__(256)
void gat_gather_kernel(float* __restrict__ out, int N) {
    int w = (int)((blockIdx.x * blockDim.x + threadIdx.x) >> 5);
    if (w >= N) return;
    int lane = threadIdx.x & 31;

    int beg = g_rowptr[w];
    int endp = g_rowptr[w + 1];
    if (beg == endp) return;

    const uint2* fjv = (const uint2*)g_fj;
    float4 acc = make_float4(0.f, 0.f, 0.f, 0.f);

    for (int base = beg; base < endp; base += 32) {
        int idx = base + lane;
        int2 pk = make_int2(0, 0);
        if (idx < endp) pk = g_edge[idx];
        int cnt = min(32, endp - base);
        for (int k = 0; k < cnt; ++k) {
            int   jj = __shfl_sync(0xffffffffu, pk.x, k);
            float aa = __int_as_float(__shfl_sync(0xffffffffu, pk.y, k));
            uint2 v = fjv[(size_t)jj * 32 + lane];
            float2 f0 = __half22float2(*(__half2*)&v.x);
            float2 f1 = __half22float2(*(__half2*)&v.y);
            acc.x = fmaf(aa, f0.x, acc.x);
            acc.y = fmaf(aa, f0.y, acc.y);
            acc.z = fmaf(aa, f1.x, acc.z);
            acc.w = fmaf(aa, f1.y, acc.w);
        }
    }

    float4* o = (float4*)&out[(size_t)w * D + lane * 4];
    float4 cur = *o;
    cur.x += acc.x; cur.y += acc.y; cur.z += acc.z; cur.w += acc.w;
    *o = cur;
}

// ---------------------------------------------------------------------------
extern "C" void kernel_launch(void* const* d_in, const int* in_sizes, int n_in,
                              void* d_out, int out_size)
{
    const float* X   = (const float*)d_in[0];
    const float* W1  = (const float*)d_in[1];
    const float* b1  = (const float*)d_in[2];
    const float* W2  = (const float*)d_in[3];
    const float* b2  = (const float*)d_in[4];
    const float* wa1 = (const float*)d_in[5];
    const float* ba1 = (const float*)d_in[6];
    const float* wa2 = (const float*)d_in[7];
    const float* ba2 = (const float*)d_in[8];
    const int*   ei  = (const int*)d_in[9];   // int32 edge_index [2, E]
    float* out = (float*)d_out;

    int N = in_sizes[0] / D;
    int E = in_sizes[9] / 2;
    int tiles = (N + 127) / 128;
    int nb = (N + 255) / 256;

    const int gemm_smem = (256 * XPAD + 2 * 128 * HPAD) * (int)sizeof(uint32_t)
                        + (128 * 4 * 2) * (int)sizeof(float);   // ~209 KB
    cudaFuncSetAttribute(gat_gemm_kernel,
                         cudaFuncAttributeMaxDynamicSharedMemorySize, gemm_smem);

    // One-time side stream + fork/join events (created on correctness run,
    // outside graph capture).
    static cudaStream_t s_side = nullptr;
    static cudaEvent_t  s_fork = nullptr, s_join = nullptr;
    if (!s_side) {
        cudaStreamCreateWithFlags(&s_side, cudaStreamNonBlocking);
        cudaEventCreateWithFlags(&s_fork, cudaEventDisableTiming);
        cudaEventCreateWithFlags(&s_join, cudaEventDisableTiming);
    }

    // Fork: CSR build (edge-only path) runs concurrently with the GEMM.
    cudaEventRecord(s_fork, 0);
    cudaStreamWaitEvent(s_side, s_fork, 0);
    hist_kernel<<<(E + 255) / 256, 256, 0, s_side>>>(ei, E, N);
    scan1_kernel<<<nb, 256, 0, s_side>>>(N);
    scanB_kernel<<<nb, 256, 0, s_side>>>(nb, N);
    cudaEventRecord(s_join, s_side);

    int gblocks = tiles < 148 ? tiles : 148;
    gat_gemm_kernel<<<gblocks, 512, gemm_smem>>>(
        X, W1, W2, b1, b2, wa1, ba1, wa2, ba2, out, N, tiles);

    // Join, then atomic-free fill + gather.
    cudaStreamWaitEvent(0, s_join, 0);
    fill_kernel<<<(E + 255) / 256, 256>>>(ei, E, N);
    gat_gather_kernel<<<(N * 32 + 255) / 256, 256>>>(out, N);
}

// round 16
// speedup vs baseline: 1.0518x; 1.0518x over previous
#include <cuda_runtime.h>
#include <cuda_bf16.h>
#include <cuda_fp16.h>
#include <cstdint>

#define D 128
#define MAXN 50000
#define MAXE 800000
#define XPAD 132   // W row pad (tf32 words)
#define HPAD 68    // X half-row pad

// Scratch (allocation-free rule: __device__ globals)
__device__ __half g_fj[MAXN * D];
__device__ float g_a1[MAXN];
__device__ float g_a2[MAXN];
__device__ int   g_cnt[MAXN];       // zeroed at end of scanB (starts zero)
__device__ int   g_rowptr[MAXN + 1];
__device__ int   g_slot[MAXE];      // within-bucket slot per edge (from hist)
__device__ int   g_col[MAXE];       // CSR column indices
__device__ int   g_bsum[256];

__device__ __forceinline__ float sigmoidf_(float x) {
    return 1.0f / (1.0f + __expf(-x));
}

__device__ __forceinline__ uint32_t f2tf32(float x) {
    uint32_t r;
    asm("cvt.rna.tf32.f32 %0, %1;" : "=r"(r) : "f"(x));
    return r;
}

__device__ __forceinline__ void mma_tf32(float& d0, float& d1, float& d2, float& d3,
                                         uint32_t a0, uint32_t a1, uint32_t a2, uint32_t a3,
                                         uint32_t b0, uint32_t b1) {
    asm volatile("mma.sync.aligned.m16n8k8.row.col.f32.tf32.tf32.f32 "
                 "{%0,%1,%2,%3},{%4,%5,%6,%7},{%8,%9},{%0,%1,%2,%3};"
                 : "+f"(d0), "+f"(d1), "+f"(d2), "+f"(d3)
                 : "r"(a0), "r"(a1), "r"(a2), "r"(a3), "r"(b0), "r"(b1));
}

#define LDSM4(r0, r1, r2, r3, addr)                                        \
    asm volatile("ldmatrix.sync.aligned.m8n8.x4.shared.b16 {%0,%1,%2,%3}, [%4];" \
                 : "=r"(r0), "=r"(r1), "=r"(r2), "=r"(r3) : "r"(addr))

// ---------------------------------------------------------------------------
// Edge histogram (side stream). Atomic return value = within-bucket slot.
// ---------------------------------------------------------------------------
__global__ __launch_bounds__(256)
void hist_kernel(const int* __restrict__ ei, int E, int N)
{
    int e = blockIdx.x * blockDim.x + threadIdx.x;
    if (e >= E) return;
    int i = ei[e];
    int slot = ((unsigned)i < (unsigned)N) ? atomicAdd(&g_cnt[i], 1) : 0;
    g_slot[e] = slot;
}

// ---------------------------------------------------------------------------
// Persistent tf32 GEMM (512 thr, 16 warps = 4 wm x 4 wn, warp tile 32x64),
// cp.async k-split double-buffered X from raw fp32 (rz trunc); W converted
// to tf32 in-kernel during staging (once per CTA).
// ---------------------------------------------------------------------------
__device__ __forceinline__ void stage_x_half(const float* __restrict__ X,
                                             int row0, int h, uint32_t xsh,
                                             int N, int tid)
{
#pragma unroll
    for (int it = 0; it < 4; ++it) {
        int idx = tid + it * 512;          // 0..2047
        int r   = idx >> 4;                // 0..127
        int c16 = idx & 15;                // 0..15 (16B units)
        int row = row0 + r;
        const float* gsrc = X + (size_t)((row < N) ? row : 0) * 128 + h * 64 + c16 * 4;
        uint32_t dst = xsh + (uint32_t)(r * HPAD + c16 * 4) * 4;
        uint32_t ssz = (row < N) ? 16u : 0u;
        asm volatile("cp.async.cg.shared.global [%0], [%1], 16, %2;"
                     :: "r"(dst), "l"(gsrc), "r"(ssz) : "memory");
    }
    asm volatile("cp.async.commit_group;" ::: "memory");
}

__device__ __forceinline__ void mma_half(float d[2][8][4],
                                         const uint32_t aaddr[2],
                                         const uint32_t baddr[4],
                                         uint32_t hoff)
{
#pragma unroll
    for (int kk = 0; kk < 8; ++kk) {
        const uint32_t koff = kk * 32;
        uint32_t a[2][4];
        LDSM4(a[0][0], a[0][1], a[0][2], a[0][3], aaddr[0] + koff);
        LDSM4(a[1][0], a[1][1], a[1][2], a[1][3], aaddr[1] + koff);
        uint32_t b[4][4];
        LDSM4(b[0][0], b[0][1], b[0][2], b[0][3], baddr[0] + hoff + koff);
        LDSM4(b[1][0], b[1][1], b[1][2], b[1][3], baddr[1] + hoff + koff);
        LDSM4(b[2][0], b[2][1], b[2][2], b[2][3], baddr[2] + hoff + koff);
        LDSM4(b[3][0], b[3][1], b[3][2], b[3][3], baddr[3] + hoff + koff);
#pragma unroll
        for (int t = 0; t < 2; ++t)
#pragma unroll
            for (int u = 0; u < 8; ++u)
                mma_tf32(d[t][u][0], d[t][u][1], d[t][u][2], d[t][u][3],
                         a[t][0], a[t][1], a[t][2], a[t][3],
                         b[u >> 1][(u & 1) * 2], b[u >> 1][(u & 1) * 2 + 1]);
    }
}

__global__ __launch_bounds__(512, 1)
void gat_gemm_kernel(const float* __restrict__ X,
                     const float* __restrict__ W1, const float* __restrict__ W2,
                     const float* __restrict__ b1, const float* __restrict__ b2,
                     const float* __restrict__ wa1, const float* __restrict__ ba1,
                     const float* __restrict__ wa2, const float* __restrict__ ba2,
                     float* __restrict__ out, int N, int tiles)
{
    extern __shared__ uint32_t smem_u[];
    uint32_t* ws  = smem_u;                          // [256][XPAD]
    uint32_t* xs0 = smem_u + 256 * XPAD;             // [128][HPAD]
    uint32_t* xs1 = xs0 + 128 * HPAD;                // [128][HPAD]
    float*    sp1 = (float*)(xs1 + 128 * HPAD);      // [128][4]
    float*    sp2 = sp1 + 128 * 4;                   // [128][4]

    const int tid  = threadIdx.x;
    const int warp = tid >> 5;
    const int lane = tid & 31;
    const int g    = lane >> 2;
    const int tig  = lane & 3;
    const int wm   = warp & 3;
    const int wn   = warp >> 2;
    const int m0   = wm * 32;

    // --- Stage W once, converting fp32 -> tf32 bits in-flight ---
    const float4* W1v = (const float4*)W1;
    const float4* W2v = (const float4*)W2;
    for (int it = 0; it < 8; ++it) {
        int idx = tid + it * 512;          // 0..4095: c 0..127, k4 0..31
        int c  = idx >> 5;
        int k4 = idx & 31;
        float4 a = W1v[c * 32 + k4];
        uint32_t* p = &ws[c * XPAD + k4 * 4];
        p[0] = f2tf32(a.x); p[1] = f2tf32(a.y); p[2] = f2tf32(a.z); p[3] = f2tf32(a.w);
        float4 b = W2v[c * 32 + k4];
        uint32_t* q = &ws[(128 + c) * XPAD + k4 * 4];
        q[0] = f2tf32(b.x); q[1] = f2tf32(b.y); q[2] = f2tf32(b.z); q[3] = f2tf32(b.w);
    }

    // --- ldmatrix per-lane addresses ---
    uint32_t aaddr[2][2];   // [buf][t]
    {
        int s = lane >> 3;
        int row = m0 + (lane & 7) + (s & 1) * 8;
        int colw = (s >> 1) * 4;
        aaddr[0][0] = (uint32_t)__cvta_generic_to_shared(&xs0[row * HPAD + colw]);
        aaddr[0][1] = (uint32_t)__cvta_generic_to_shared(&xs0[(row + 16) * HPAD + colw]);
        aaddr[1][0] = (uint32_t)__cvta_generic_to_shared(&xs1[row * HPAD + colw]);
        aaddr[1][1] = (uint32_t)__cvta_generic_to_shared(&xs1[(row + 16) * HPAD + colw]);
    }
    uint32_t baddr[4];
    {
        int s = lane >> 3;
        int khw = (s & 1) * 4;
#pragma unroll
        for (int p = 0; p < 4; ++p) {
            int u = 2 * p + (s >> 1);
            int n = (u < 4) ? (wn * 32 + u * 8) : (128 + wn * 32 + (u - 4) * 8);
            baddr[p] = (uint32_t)__cvta_generic_to_shared(&ws[(n + (lane & 7)) * XPAD + khw]);
        }
    }
    uint32_t xsh[2] = { (uint32_t)__cvta_generic_to_shared(xs0),
                        (uint32_t)__cvta_generic_to_shared(xs1) };

    // Per-thread epilogue constants
    float2 bb1[4], bb2[4], v1[4], v2[4];
#pragma unroll
    for (int u = 0; u < 4; ++u) {
        int c = wn * 32 + u * 8 + tig * 2;
        bb1[u] = *(const float2*)&b1[c];
        bb2[u] = *(const float2*)&b2[c];
        v1[u]  = *(const float2*)&wa1[c];
        v2[u]  = *(const float2*)&wa2[c];
    }
    const float bba1 = ba1[0];
    const float bba2 = ba2[0];

    int tile = blockIdx.x;
    stage_x_half(X, tile * 128, 0, xsh[0], N, tid);

    for (; tile < tiles; tile += gridDim.x) {
        const int row0 = tile * 128;

        stage_x_half(X, row0, 1, xsh[1], N, tid);
        asm volatile("cp.async.wait_group 1;" ::: "memory");   // half0 ready
        __syncthreads();                                       // S1 (also W visible)

        float d[2][8][4];
#pragma unroll
        for (int t = 0; t < 2; ++t)
#pragma unroll
            for (int u = 0; u < 8; ++u)
#pragma unroll
                for (int e = 0; e < 4; ++e) d[t][u][e] = 0.f;

        mma_half(d, aaddr[0], baddr, 0);
        __syncthreads();                                       // S2: buf0 free

        int ntile = tile + gridDim.x;
        if (ntile < tiles) {
            stage_x_half(X, ntile * 128, 0, xsh[0], N, tid);
            asm volatile("cp.async.wait_group 1;" ::: "memory"); // half1 ready
        } else {
            asm volatile("cp.async.wait_group 0;" ::: "memory");
        }
        __syncthreads();                                       // S3

        mma_half(d, aaddr[1], baddr, 64 * 4);

        // --- Dot partials, reduce over tig, stash per (row, wn) ---
        float p1[2][2] = {{0.f, 0.f}, {0.f, 0.f}};
        float p2[2][2] = {{0.f, 0.f}, {0.f, 0.f}};
#pragma unroll
        for (int t = 0; t < 2; ++t)
#pragma unroll
            for (int u = 0; u < 4; ++u) {
                float fi0 = fmaxf(d[t][u][0] + bb1[u].x, 0.f);
                float fi1 = fmaxf(d[t][u][1] + bb1[u].y, 0.f);
                float fi2 = fmaxf(d[t][u][2] + bb1[u].x, 0.f);
                float fi3 = fmaxf(d[t][u][3] + bb1[u].y, 0.f);
                float fj0 = fmaxf(d[t][u + 4][0] + bb2[u].x, 0.f);
                float fj1 = fmaxf(d[t][u + 4][1] + bb2[u].y, 0.f);
                float fj2 = fmaxf(d[t][u + 4][2] + bb2[u].x, 0.f);
                float fj3 = fmaxf(d[t][u + 4][3] + bb2[u].y, 0.f);
                p1[t][0] = fmaf(fi0, v1[u].x, fmaf(fi1, v1[u].y, p1[t][0]));
                p1[t][1] = fmaf(fi2, v1[u].x, fmaf(fi3, v1[u].y, p1[t][1]));
                p2[t][0] = fmaf(fj0, v2[u].x, fmaf(fj1, v2[u].y, p2[t][0]));
                p2[t][1] = fmaf(fj2, v2[u].x, fmaf(fj3, v2[u].y, p2[t][1]));
            }
#pragma unroll
        for (int off = 1; off <= 2; off <<= 1)
#pragma unroll
            for (int t = 0; t < 2; ++t)
#pragma unroll
                for (int h = 0; h < 2; ++h) {
                    p1[t][h] += __shfl_xor_sync(0xffffffffu, p1[t][h], off);
                    p2[t][h] += __shfl_xor_sync(0xffffffffu, p2[t][h], off);
                }
        if (tig == 0) {
#pragma unroll
            for (int t = 0; t < 2; ++t)
#pragma unroll
                for (int h = 0; h < 2; ++h) {
                    int r = m0 + t * 16 + g + h * 8;
                    sp1[r * 4 + wn] = p1[t][h];
                    sp2[r * 4 + wn] = p2[t][h];
                }
        }
        __syncthreads();                                       // S4: partials

        // --- att per thread; stores ---
#pragma unroll
        for (int t = 0; t < 2; ++t)
#pragma unroll
            for (int h = 0; h < 2; ++h) {
                int r = m0 + t * 16 + g + h * 8;
                int gr = row0 + r;
                if (gr >= N) continue;
                float a1v = sp1[r * 4] + sp1[r * 4 + 1] + sp1[r * 4 + 2] + sp1[r * 4 + 3] + bba1;
                float a2v = sp2[r * 4] + sp2[r * 4 + 1] + sp2[r * 4 + 2] + sp2[r * 4 + 3] + bba2;
                float att = sigmoidf_(a1v + a2v);
                if (wn == 0 && tig == 0) { g_a1[gr] = a1v; g_a2[gr] = a2v; }
                float*  orow = out  + (size_t)gr * D;
                __half* jrow = g_fj + (size_t)gr * D;
#pragma unroll
                for (int u = 0; u < 4; ++u) {
                    int c = wn * 32 + u * 8 + tig * 2;
                    int e0 = h * 2, e1 = h * 2 + 1;
                    float fj0 = fmaxf(d[t][u + 4][e0] + bb2[u].x, 0.f);
                    float fj1 = fmaxf(d[t][u + 4][e1] + bb2[u].y, 0.f);
                    float o0 = fmaf(att, fj0, fmaxf(d[t][u][e0] + bb1[u].x, 0.f));
                    float o1 = fmaf(att, fj1, fmaxf(d[t][u][e1] + bb1[u].y, 0.f));
                    *(float2*)&orow[c] = make_float2(o0, o1);
                    *(__half2*)&jrow[c] = __floats2half2_rn(fj0, fj1);
                }
            }
    }
}

// ---------------------------------------------------------------------------
// CSR build (ALL on side stream: hist -> scan1 -> scanB -> fill_col).
// None of it depends on the GEMM.
// ---------------------------------------------------------------------------
__global__ __launch_bounds__(256)
void scan1_kernel(int N) {
    __shared__ int red[256];
    int i = blockIdx.x * 256 + threadIdx.x;
    int v = (i < N) ? g_cnt[i] : 0;
    red[threadIdx.x] = v;
    __syncthreads();
    for (int off = 128; off >= 1; off >>= 1) {
        if (threadIdx.x < off) red[threadIdx.x] += red[threadIdx.x + off];
        __syncthreads();
    }
    if (threadIdx.x == 0) g_bsum[blockIdx.x] = red[0];
}

__global__ __launch_bounds__(256)
void scanB_kernel(int nb, int N) {
    __shared__ int p[256];
    __shared__ int boff;
    const int t = threadIdx.x;

    int v = (t < nb) ? g_bsum[t] : 0;
    p[t] = v;
    __syncthreads();
    for (int off = 1; off < 256; off <<= 1) {
        int u = (t >= off) ? p[t - off] : 0;
        __syncthreads();
        p[t] += u;
        __syncthreads();
    }
    if (t == (int)blockIdx.x) boff = p[t] - v;
    if (blockIdx.x == 0 && t == nb - 1) g_rowptr[N] = p[t];
    __syncthreads();

    int i = blockIdx.x * 256 + t;
    int c = (i < N) ? g_cnt[i] : 0;
    p[t] = c;
    __syncthreads();
    for (int off = 1; off < 256; off <<= 1) {
        int u = (t >= off) ? p[t - off] : 0;
        __syncthreads();
        p[t] += u;
        __syncthreads();
    }
    if (i < N) {
        g_rowptr[i] = p[t] - c + boff;
        g_cnt[i] = 0;      // leave zeroed for next launch (determinism)
    }
}

// Fill CSR columns only (no att): pos = rowptr[i] + slot[e].
__global__ void fill_kernel(const int* __restrict__ ei, int E, int N) {
    int e = blockIdx.x * blockDim.x + threadIdx.x;
    if (e >= E) return;
    int i = ei[e];
    int j = ei[E + e];
    if ((unsigned)i >= (unsigned)N || (unsigned)j >= (unsigned)N) return;
    g_col[g_rowptr[i] + g_slot[e]] = j;
}

// ---------------------------------------------------------------------------
// Gather: one warp per node. att computed in the LANE-PARALLEL staging phase
// (32 edges at once), then shfl-broadcast with the column index.
// ---------------------------------------------------------------------------
__global__ __launch_bounds__(256)
void gat_gather_kernel(float* __restrict__ out, int N) {
    int w = (int)((blockIdx.x * blockDim.x + threadIdx.x) >> 5);
    if (w >= N) return;
    int lane = threadIdx.x & 31;

    int beg = g_rowptr[w];
    int endp = g_rowptr[w + 1];
    if (beg == endp) return;

    const float a1i = g_a1[w];
    const uint2* fjv = (const uint2*)g_fj;
    float4 acc = make_float4(0.f, 0.f, 0.f, 0.f);

    for (int base = beg; base < endp; base += 32) {
        int idx = base + lane;
        int j = 0;
        float att = 0.f;
        if (idx < endp) {
            j = g_col[idx];
            att = sigmoidf_(a1i + __ldg(&g_a2[j]));
        }
        int cnt = min(32, endp - base);
        for (int k = 0; k < cnt; ++k) {
            int   jj = __shfl_sync(0xffffffffu, j, k);
            float aa = __shfl_sync(0xffffffffu, att, k);
            uint2 v = fjv[(size_t)jj * 32 + lane];
            float2 f0 = __half22float2(*(__half2*)&v.x);
            float2 f1 = __half22float2(*(__half2*)&v.y);
            acc.x = fmaf(aa, f0.x, acc.x);
            acc.y = fmaf(aa, f0.y, acc.y);
            acc.z = fmaf(aa, f1.x, acc.z);
            acc.w = fmaf(aa, f1.y, acc.w);
        }
    }

    float4* o = (float4*)&out[(size_t)w * D + lane * 4];
    float4 cur = *o;
    cur.x += acc.x; cur.y += acc.y; cur.z += acc.z; cur.w += acc.w;
    *o = cur;
}

// ---------------------------------------------------------------------------
extern "C" void kernel_launch(void* const* d_in, const int* in_sizes, int n_in,
                              void* d_out, int out_size)
{
    const float* X   = (const float*)d_in[0];
    const float* W1  = (const float*)d_in[1];
    const float* b1  = (const float*)d_in[2];
    const float* W2  = (const float*)d_in[3];
    const float* b2  = (const float*)d_in[4];
    const float* wa1 = (const float*)d_in[5];
    const float* ba1 = (const float*)d_in[6];
    const float* wa2 = (const float*)d_in[7];
    const float* ba2 = (const float*)d_in[8];
    const int*   ei  = (const int*)d_in[9];   // int32 edge_index [2, E]
    float* out = (float*)d_out;

    int N = in_sizes[0] / D;
    int E = in_sizes[9] / 2;
    int tiles = (N + 127) / 128;
    int nb = (N + 255) / 256;

    const int gemm_smem = (256 * XPAD + 2 * 128 * HPAD) * (int)sizeof(uint32_t)
                        + (128 * 4 * 2) * (int)sizeof(float);   // ~209 KB
    cudaFuncSetAttribute(gat_gemm_kernel,
                         cudaFuncAttributeMaxDynamicSharedMemorySize, gemm_smem);

    // One-time side stream + fork/join events (created on correctness run,
    // outside graph capture).
    static cudaStream_t s_side = nullptr;
    static cudaEvent_t  s_fork = nullptr, s_join = nullptr;
    if (!s_side) {
        cudaStreamCreateWithFlags(&s_side, cudaStreamNonBlocking);
        cudaEventCreateWithFlags(&s_fork, cudaEventDisableTiming);
        cudaEventCreateWithFlags(&s_join, cudaEventDisableTiming);
    }

    // Fork: ENTIRE CSR build (edge-only) runs concurrently with the GEMM.
    cudaEventRecord(s_fork, 0);
    cudaStreamWaitEvent(s_side, s_fork, 0);
    hist_kernel<<<(E + 255) / 256, 256, 0, s_side>>>(ei, E, N);
    scan1_kernel<<<nb, 256, 0, s_side>>>(N);
    scanB_kernel<<<nb, 256, 0, s_side>>>(nb, N);
    fill_kernel<<<(E + 255) / 256, 256, 0, s_side>>>(ei, E, N);
    cudaEventRecord(s_join, s_side);

    int gblocks = tiles < 148 ? tiles : 148;
    gat_gemm_kernel<<<gblocks, 512, gemm_smem>>>(
        X, W1, W2, b1, b2, wa1, ba1, wa2, ba2, out, N, tiles);

    // Join, then gather (computes att on the fly, lane-parallel).
    cudaStreamWaitEvent(0, s_join, 0);
    gat_gather_kernel<<<(N * 32 + 255) / 256, 256>>>(out, N);
}

// round 17
// speedup vs baseline: 1.0769x; 1.0238x over previous
#include <cuda_runtime.h>
#include <cuda_bf16.h>
#include <cuda_fp16.h>
#include <cstdint>

#define D 128
#define MAXN 50000
#define MAXE 800000
#define XPAD 132   // W row pad (tf32 words)
#define HPAD 68    // X half-row pad

// Scratch (allocation-free rule: __device__ globals)
__device__ __half g_fj[MAXN * D];
__device__ float g_a1[MAXN];
__device__ float g_a2[MAXN];
__device__ int   g_cnt[MAXN];       // zeroed at end of scanB (starts zero)
__device__ int   g_rowptr[MAXN + 1];
__device__ int   g_slot[MAXE];      // within-bucket slot per edge (from hist)
__device__ int   g_col[MAXE];       // CSR column indices
__device__ int   g_bsum[256];

__device__ __forceinline__ float sigmoidf_(float x) {
    return 1.0f / (1.0f + __expf(-x));
}

__device__ __forceinline__ uint32_t f2tf32(float x) {
    uint32_t r;
    asm("cvt.rna.tf32.f32 %0, %1;" : "=r"(r) : "f"(x));
    return r;
}

__device__ __forceinline__ void mma_tf32(float& d0, float& d1, float& d2, float& d3,
                                         uint32_t a0, uint32_t a1, uint32_t a2, uint32_t a3,
                                         uint32_t b0, uint32_t b1) {
    asm volatile("mma.sync.aligned.m16n8k8.row.col.f32.tf32.tf32.f32 "
                 "{%0,%1,%2,%3},{%4,%5,%6,%7},{%8,%9},{%0,%1,%2,%3};"
                 : "+f"(d0), "+f"(d1), "+f"(d2), "+f"(d3)
                 : "r"(a0), "r"(a1), "r"(a2), "r"(a3), "r"(b0), "r"(b1));
}

#define LDSM4(r0, r1, r2, r3, addr)                                        \
    asm volatile("ldmatrix.sync.aligned.m8n8.x4.shared.b16 {%0,%1,%2,%3}, [%4];" \
                 : "=r"(r0), "=r"(r1), "=r"(r2), "=r"(r3) : "r"(addr))

// ---------------------------------------------------------------------------
// Edge histogram (side stream). Atomic return value = within-bucket slot.
// ---------------------------------------------------------------------------
__global__ __launch_bounds__(256)
void hist_kernel(const int* __restrict__ ei, int E, int N)
{
    int e = blockIdx.x * blockDim.x + threadIdx.x;
    if (e >= E) return;
    int i = ei[e];
    int slot = ((unsigned)i < (unsigned)N) ? atomicAdd(&g_cnt[i], 1) : 0;
    g_slot[e] = slot;
}

// ---------------------------------------------------------------------------
// Persistent tf32 GEMM (512 thr, 16 warps = 4 wm x 4 wn, warp tile 32x64),
// cp.async k-split double-buffered X from raw fp32 (rz trunc); W converted
// to tf32 in-kernel during staging (once per CTA).
// Grid = ceil(tiles/3): same 3-tile critical path as 148, frees ~17 SMs
// for the concurrent CSR side stream (GEMM's 512x128 regs fill the RF, so
// side kernels can never co-reside on a GEMM SM).
// ---------------------------------------------------------------------------
__device__ __forceinline__ void stage_x_half(const float* __restrict__ X,
                                             int row0, int h, uint32_t xsh,
                                             int N, int tid)
{
#pragma unroll
    for (int it = 0; it < 4; ++it) {
        int idx = tid + it * 512;          // 0..2047
        int r   = idx >> 4;                // 0..127
        int c16 = idx & 15;                // 0..15 (16B units)
        int row = row0 + r;
        const float* gsrc = X + (size_t)((row < N) ? row : 0) * 128 + h * 64 + c16 * 4;
        uint32_t dst = xsh + (uint32_t)(r * HPAD + c16 * 4) * 4;
        uint32_t ssz = (row < N) ? 16u : 0u;
        asm volatile("cp.async.cg.shared.global [%0], [%1], 16, %2;"
                     :: "r"(dst), "l"(gsrc), "r"(ssz) : "memory");
    }
    asm volatile("cp.async.commit_group;" ::: "memory");
}

__device__ __forceinline__ void mma_half(float d[2][8][4],
                                         const uint32_t aaddr[2],
                                         const uint32_t baddr[4],
                                         uint32_t hoff)
{
#pragma unroll
    for (int kk = 0; kk < 8; ++kk) {
        const uint32_t koff = kk * 32;
        uint32_t a[2][4];
        LDSM4(a[0][0], a[0][1], a[0][2], a[0][3], aaddr[0] + koff);
        LDSM4(a[1][0], a[1][1], a[1][2], a[1][3], aaddr[1] + koff);
        uint32_t b[4][4];
        LDSM4(b[0][0], b[0][1], b[0][2], b[0][3], baddr[0] + hoff + koff);
        LDSM4(b[1][0], b[1][1], b[1][2], b[1][3], baddr[1] + hoff + koff);
        LDSM4(b[2][0], b[2][1], b[2][2], b[2][3], baddr[2] + hoff + koff);
        LDSM4(b[3][0], b[3][1], b[3][2], b[3][3], baddr[3] + hoff + koff);
#pragma unroll
        for (int t = 0; t < 2; ++t)
#pragma unroll
            for (int u = 0; u < 8; ++u)
                mma_tf32(d[t][u][0], d[t][u][1], d[t][u][2], d[t][u][3],
                         a[t][0], a[t][1], a[t][2], a[t][3],
                         b[u >> 1][(u & 1) * 2], b[u >> 1][(u & 1) * 2 + 1]);
    }
}

__global__ __launch_bounds__(512, 1)
void gat_gemm_kernel(const float* __restrict__ X,
                     const float* __restrict__ W1, const float* __restrict__ W2,
                     const float* __restrict__ b1, const float* __restrict__ b2,
                     const float* __restrict__ wa1, const float* __restrict__ ba1,
                     const float* __restrict__ wa2, const float* __restrict__ ba2,
                     float* __restrict__ out, int N, int tiles)
{
    extern __shared__ uint32_t smem_u[];
    uint32_t* ws  = smem_u;                          // [256][XPAD]
    uint32_t* xs0 = smem_u + 256 * XPAD;             // [128][HPAD]
    uint32_t* xs1 = xs0 + 128 * HPAD;                // [128][HPAD]
    float*    sp1 = (float*)(xs1 + 128 * HPAD);      // [128][4]
    float*    sp2 = sp1 + 128 * 4;                   // [128][4]

    const int tid  = threadIdx.x;
    const int warp = tid >> 5;
    const int lane = tid & 31;
    const int g    = lane >> 2;
    const int tig  = lane & 3;
    const int wm   = warp & 3;
    const int wn   = warp >> 2;
    const int m0   = wm * 32;

    // --- Stage W once, converting fp32 -> tf32 bits in-flight ---
    const float4* W1v = (const float4*)W1;
    const float4* W2v = (const float4*)W2;
    for (int it = 0; it < 8; ++it) {
        int idx = tid + it * 512;          // 0..4095: c 0..127, k4 0..31
        int c  = idx >> 5;
        int k4 = idx & 31;
        float4 a = W1v[c * 32 + k4];
        uint32_t* p = &ws[c * XPAD + k4 * 4];
        p[0] = f2tf32(a.x); p[1] = f2tf32(a.y); p[2] = f2tf32(a.z); p[3] = f2tf32(a.w);
        float4 b = W2v[c * 32 + k4];
        uint32_t* q = &ws[(128 + c) * XPAD + k4 * 4];
        q[0] = f2tf32(b.x); q[1] = f2tf32(b.y); q[2] = f2tf32(b.z); q[3] = f2tf32(b.w);
    }

    // --- ldmatrix per-lane addresses ---
    uint32_t aaddr[2][2];   // [buf][t]
    {
        int s = lane >> 3;
        int row = m0 + (lane & 7) + (s & 1) * 8;
        int colw = (s >> 1) * 4;
        aaddr[0][0] = (uint32_t)__cvta_generic_to_shared(&xs0[row * HPAD + colw]);
        aaddr[0][1] = (uint32_t)__cvta_generic_to_shared(&xs0[(row + 16) * HPAD + colw]);
        aaddr[1][0] = (uint32_t)__cvta_generic_to_shared(&xs1[row * HPAD + colw]);
        aaddr[1][1] = (uint32_t)__cvta_generic_to_shared(&xs1[(row + 16) * HPAD + colw]);
    }
    uint32_t baddr[4];
    {
        int s = lane >> 3;
        int khw = (s & 1) * 4;
#pragma unroll
        for (int p = 0; p < 4; ++p) {
            int u = 2 * p + (s >> 1);
            int n = (u < 4) ? (wn * 32 + u * 8) : (128 + wn * 32 + (u - 4) * 8);
            baddr[p] = (uint32_t)__cvta_generic_to_shared(&ws[(n + (lane & 7)) * XPAD + khw]);
        }
    }
    uint32_t xsh[2] = { (uint32_t)__cvta_generic_to_shared(xs0),
                        (uint32_t)__cvta_generic_to_shared(xs1) };

    // Per-thread epilogue constants
    float2 bb1[4], bb2[4], v1[4], v2[4];
#pragma unroll
    for (int u = 0; u < 4; ++u) {
        int c = wn * 32 + u * 8 + tig * 2;
        bb1[u] = *(const float2*)&b1[c];
        bb2[u] = *(const float2*)&b2[c];
        v1[u]  = *(const float2*)&wa1[c];
        v2[u]  = *(const float2*)&wa2[c];
    }
    const float bba1 = ba1[0];
    const float bba2 = ba2[0];

    int tile = blockIdx.x;
    stage_x_half(X, tile * 128, 0, xsh[0], N, tid);

    for (; tile < tiles; tile += gridDim.x) {
        const int row0 = tile * 128;

        stage_x_half(X, row0, 1, xsh[1], N, tid);
        asm volatile("cp.async.wait_group 1;" ::: "memory");   // half0 ready
        __syncthreads();                                       // S1 (also W visible)

        float d[2][8][4];
#pragma unroll
        for (int t = 0; t < 2; ++t)
#pragma unroll
            for (int u = 0; u < 8; ++u)
#pragma unroll
                for (int e = 0; e < 4; ++e) d[t][u][e] = 0.f;

        mma_half(d, aaddr[0], baddr, 0);
        __syncthreads();                                       // S2: buf0 free

        int ntile = tile + gridDim.x;
        if (ntile < tiles) {
            stage_x_half(X, ntile * 128, 0, xsh[0], N, tid);
            asm volatile("cp.async.wait_group 1;" ::: "memory"); // half1 ready
        } else {
            asm volatile("cp.async.wait_group 0;" ::: "memory");
        }
        __syncthreads();                                       // S3

        mma_half(d, aaddr[1], baddr, 64 * 4);

        // --- Dot partials, reduce over tig, stash per (row, wn) ---
        float p1[2][2] = {{0.f, 0.f}, {0.f, 0.f}};
        float p2[2][2] = {{0.f, 0.f}, {0.f, 0.f}};
#pragma unroll
        for (int t = 0; t < 2; ++t)
#pragma unroll
            for (int u = 0; u < 4; ++u) {
                float fi0 = fmaxf(d[t][u][0] + bb1[u].x, 0.f);
                float fi1 = fmaxf(d[t][u][1] + bb1[u].y, 0.f);
                float fi2 = fmaxf(d[t][u][2] + bb1[u].x, 0.f);
                float fi3 = fmaxf(d[t][u][3] + bb1[u].y, 0.f);
                float fj0 = fmaxf(d[t][u + 4][0] + bb2[u].x, 0.f);
                float fj1 = fmaxf(d[t][u + 4][1] + bb2[u].y, 0.f);
                float fj2 = fmaxf(d[t][u + 4][2] + bb2[u].x, 0.f);
                float fj3 = fmaxf(d[t][u + 4][3] + bb2[u].y, 0.f);
                p1[t][0] = fmaf(fi0, v1[u].x, fmaf(fi1, v1[u].y, p1[t][0]));
                p1[t][1] = fmaf(fi2, v1[u].x, fmaf(fi3, v1[u].y, p1[t][1]));
                p2[t][0] = fmaf(fj0, v2[u].x, fmaf(fj1, v2[u].y, p2[t][0]));
                p2[t][1] = fmaf(fj2, v2[u].x, fmaf(fj3, v2[u].y, p2[t][1]));
            }
#pragma unroll
        for (int off = 1; off <= 2; off <<= 1)
#pragma unroll
            for (int t = 0; t < 2; ++t)
#pragma unroll
                for (int h = 0; h < 2; ++h) {
                    p1[t][h] += __shfl_xor_sync(0xffffffffu, p1[t][h], off);
                    p2[t][h] += __shfl_xor_sync(0xffffffffu, p2[t][h], off);
                }
        if (tig == 0) {
#pragma unroll
            for (int t = 0; t < 2; ++t)
#pragma unroll
                for (int h = 0; h < 2; ++h) {
                    int r = m0 + t * 16 + g + h * 8;
                    sp1[r * 4 + wn] = p1[t][h];
                    sp2[r * 4 + wn] = p2[t][h];
                }
        }
        __syncthreads();                                       // S4: partials

        // --- att per thread; stores ---
#pragma unroll
        for (int t = 0; t < 2; ++t)
#pragma unroll
            for (int h = 0; h < 2; ++h) {
                int r = m0 + t * 16 + g + h * 8;
                int gr = row0 + r;
                if (gr >= N) continue;
                float a1v = sp1[r * 4] + sp1[r * 4 + 1] + sp1[r * 4 + 2] + sp1[r * 4 + 3] + bba1;
                float a2v = sp2[r * 4] + sp2[r * 4 + 1] + sp2[r * 4 + 2] + sp2[r * 4 + 3] + bba2;
                float att = sigmoidf_(a1v + a2v);
                if (wn == 0 && tig == 0) { g_a1[gr] = a1v; g_a2[gr] = a2v; }
                float*  orow = out  + (size_t)gr * D;
                __half* jrow = g_fj + (size_t)gr * D;
#pragma unroll
                for (int u = 0; u < 4; ++u) {
                    int c = wn * 32 + u * 8 + tig * 2;
                    int e0 = h * 2, e1 = h * 2 + 1;
                    float fj0 = fmaxf(d[t][u + 4][e0] + bb2[u].x, 0.f);
                    float fj1 = fmaxf(d[t][u + 4][e1] + bb2[u].y, 0.f);
                    float o0 = fmaf(att, fj0, fmaxf(d[t][u][e0] + bb1[u].x, 0.f));
                    float o1 = fmaf(att, fj1, fmaxf(d[t][u][e1] + bb1[u].y, 0.f));
                    *(float2*)&orow[c] = make_float2(o0, o1);
                    *(__half2*)&jrow[c] = __floats2half2_rn(fj0, fj1);
                }
            }
    }
}

// ---------------------------------------------------------------------------
// CSR build (ALL on side stream: hist -> scan1 -> scanB -> fill_col).
// ---------------------------------------------------------------------------
__global__ __launch_bounds__(256)
void scan1_kernel(int N) {
    __shared__ int red[256];
    int i = blockIdx.x * 256 + threadIdx.x;
    int v = (i < N) ? g_cnt[i] : 0;
    red[threadIdx.x] = v;
    __syncthreads();
    for (int off = 128; off >= 1; off >>= 1) {
        if (threadIdx.x < off) red[threadIdx.x] += red[threadIdx.x + off];
        __syncthreads();
    }
    if (threadIdx.x == 0) g_bsum[blockIdx.x] = red[0];
}

__global__ __launch_bounds__(256)
void scanB_kernel(int nb, int N) {
    __shared__ int p[256];
    __shared__ int boff;
    const int t = threadIdx.x;

    int v = (t < nb) ? g_bsum[t] : 0;
    p[t] = v;
    __syncthreads();
    for (int off = 1; off < 256; off <<= 1) {
        int u = (t >= off) ? p[t - off] : 0;
        __syncthreads();
        p[t] += u;
        __syncthreads();
    }
    if (t == (int)blockIdx.x) boff = p[t] - v;
    if (blockIdx.x == 0 && t == nb - 1) g_rowptr[N] = p[t];
    __syncthreads();

    int i = blockIdx.x * 256 + t;
    int c = (i < N) ? g_cnt[i] : 0;
    p[t] = c;
    __syncthreads();
    for (int off = 1; off < 256; off <<= 1) {
        int u = (t >= off) ? p[t - off] : 0;
        __syncthreads();
        p[t] += u;
        __syncthreads();
    }
    if (i < N) {
        g_rowptr[i] = p[t] - c + boff;
        g_cnt[i] = 0;      // leave zeroed for next launch (determinism)
    }
}

// Fill CSR columns only (no att): pos = rowptr[i] + slot[e].
__global__ void fill_kernel(const int* __restrict__ ei, int E, int N) {
    int e = blockIdx.x * blockDim.x + threadIdx.x;
    if (e >= E) return;
    int i = ei[e];
    int j = ei[E + e];
    if ((unsigned)i >= (unsigned)N || (unsigned)j >= (unsigned)N) return;
    g_col[g_rowptr[i] + g_slot[e]] = j;
}

// ---------------------------------------------------------------------------
// Gather: one warp per node; att computed lane-parallel in staging, then
// shfl-broadcast with the column index.
// ---------------------------------------------------------------------------
__global__ __launch_bounds__(256)
void gat_gather_kernel(float* __restrict__ out, int N) {
    int w = (int)((blockIdx.x * blockDim.x + threadIdx.x) >> 5);
    if (w >= N) return;
    int lane = threadIdx.x & 31;

    int beg = g_rowptr[w];
    int endp = g_rowptr[w + 1];
    if (beg == endp) return;

    const float a1i = g_a1[w];
    const uint2* fjv = (const uint2*)g_fj;
    float4 acc = make_float4(0.f, 0.f, 0.f, 0.f);

    for (int base = beg; base < endp; base += 32) {
        int idx = base + lane;
        int j = 0;
        float att = 0.f;
        if (idx < endp) {
            j = g_col[idx];
            att = sigmoidf_(a1i + __ldg(&g_a2[j]));
        }
        int cnt = min(32, endp - base);
        for (int k = 0; k < cnt; ++k) {
            int   jj = __shfl_sync(0xffffffffu, j, k);
            float aa = __shfl_sync(0xffffffffu, att, k);
            uint2 v = fjv[(size_t)jj * 32 + lane];
            float2 f0 = __half22float2(*(__half2*)&v.x);
            float2 f1 = __half22float2(*(__half2*)&v.y);
            acc.x = fmaf(aa, f0.x, acc.x);
            acc.y = fmaf(aa, f0.y, acc.y);
            acc.z = fmaf(aa, f1.x, acc.z);
            acc.w = fmaf(aa, f1.y, acc.w);
        }
    }

    float4* o = (float4*)&out[(size_t)w * D + lane * 4];
    float4 cur = *o;
    cur.x += acc.x; cur.y += acc.y; cur.z += acc.z; cur.w += acc.w;
    *o = cur;
}

// ---------------------------------------------------------------------------
extern "C" void kernel_launch(void* const* d_in, const int* in_sizes, int n_in,
                              void* d_out, int out_size)
{
    const float* X   = (const float*)d_in[0];
    const float* W1  = (const float*)d_in[1];
    const float* b1  = (const float*)d_in[2];
    const float* W2  = (const float*)d_in[3];
    const float* b2  = (const float*)d_in[4];
    const float* wa1 = (const float*)d_in[5];
    const float* ba1 = (const float*)d_in[6];
    const float* wa2 = (const float*)d_in[7];
    const float* ba2 = (const float*)d_in[8];
    const int*   ei  = (const int*)d_in[9];   // int32 edge_index [2, E]
    float* out = (float*)d_out;

    int N = in_sizes[0] / D;
    int E = in_sizes[9] / 2;
    int tiles = (N + 127) / 128;
    int nb = (N + 255) / 256;

    const int gemm_smem = (256 * XPAD + 2 * 128 * HPAD) * (int)sizeof(uint32_t)
                        + (128 * 4 * 2) * (int)sizeof(float);   // ~209 KB
    cudaFuncSetAttribute(gat_gemm_kernel,
                         cudaFuncAttributeMaxDynamicSharedMemorySize, gemm_smem);

    // One-time side stream + fork/join events (created on correctness run,
    // outside graph capture).
    static cudaStream_t s_side = nullptr;
    static cudaEvent_t  s_fork = nullptr, s_join = nullptr;
    if (!s_side) {
        cudaStreamCreateWithFlags(&s_side, cudaStreamNonBlocking);
        cudaEventCreateWithFlags(&s_fork, cudaEventDisableTiming);
        cudaEventCreateWithFlags(&s_join, cudaEventDisableTiming);
    }

    // Fork: ENTIRE CSR build (edge-only) runs concurrently with the GEMM.
    cudaEventRecord(s_fork, 0);
    cudaStreamWaitEvent(s_side, s_fork, 0);
    hist_kernel<<<(E + 255) / 256, 256, 0, s_side>>>(ei, E, N);
    scan1_kernel<<<nb, 256, 0, s_side>>>(N);
    scanB_kernel<<<nb, 256, 0, s_side>>>(nb, N);
    fill_kernel<<<(E + 255) / 256, 256, 0, s_side>>>(ei, E, N);
    cudaEventRecord(s_join, s_side);

    // Grid = ceil(tiles/3): same 3-tile critical path as a 148-CTA launch,
    // but leaves ~17 SMs genuinely free for the side stream (GEMM CTAs fill
    // the whole RF, so co-residency is impossible).
    int gblocks = (tiles + 2) / 3;
    if (gblocks > 148) gblocks = 148;
    gat_gemm_kernel<<<gblocks, 512, gemm_smem>>>(
        X, W1, W2, b1, b2, wa1, ba1, wa2, ba2, out, N, tiles);

    // Join, then gather (computes att on the fly, lane-parallel).
    cudaStreamWaitEvent(0, s_join, 0);
    gat_gather_kernel<<<(N * 32 + 255) / 256, 256>>>(out, N);
}